// round 14
// baseline (speedup 1.0000x reference)
#include <cuda_runtime.h>
#include <cstdint>

constexpr int B_ = 32;
constexpr int Q_ = 16384;
constexpr int G_ = 128;
constexpr int N_ = 9;
constexpr int HALF_Q = Q_ / 2;         // 8192 per warp
constexpr int GROUPS = HALF_Q / 128;   // 64 groups of 4x32 candidates

#define FULLM 0xFFFFFFFFu
#define PADF  1e-5f   // >> 5e-7 worst-case |fma-chain d2 - rn-chain d2|, d2<=4

// Full ascending bitonic sort of one 64-bit key per lane.
__device__ __forceinline__ uint64_t sort32_asc(uint64_t skey, int lane) {
#pragma unroll
    for (int k = 2; k <= 32; k <<= 1) {
#pragma unroll
        for (int j = k >> 1; j; j >>= 1) {
            const uint64_t o = __shfl_xor_sync(FULLM, skey, j);
            const bool lower = (lane & j) == 0;
            const bool asc   = (lane & k) == 0;
            const uint64_t mnv = (skey < o) ? skey : o;
            const uint64_t mxv = (skey < o) ? o : skey;
            skey = (lower == asc) ? mnv : mxv;
        }
    }
    return skey;
}

// Exact XLA-matching rn-chain d2 (no contraction).
#define EXACTD2(dst, P, GV) { \
    const float dx_ = __fsub_rn((GV).x, (P).x); \
    const float dy_ = __fsub_rn((GV).y, (P).y); \
    const float dw_ = __fsub_rn((GV).z, (P).z); \
    const float dh_ = __fsub_rn((GV).w, (P).w); \
    dst = __fadd_rn(__fadd_rn(__fadd_rn( \
              __fmul_rn(dx_, dx_), __fmul_rn(dy_, dy_)), \
              __fmul_rn(dw_, dw_)), __fmul_rn(dh_, dh_)); }

// Cheap screening d2: contraction allowed (ptxas emits FFMA chain).
#define SCREEND2(dst, P, GV) { \
    const float dx_ = (GV).x - (P).x; \
    const float dy_ = (GV).y - (P).y; \
    const float dw_ = (GV).z - (P).z; \
    const float dh_ = (GV).w - (P).w; \
    dst = fmaf(dh_, dh_, fmaf(dw_, dw_, fmaf(dy_, dy_, dx_ * dx_))); }

__global__ void __launch_bounds__(128, 12)     // cap regs ~42, occ >= 60%
atss_kernel(const float4* __restrict__ pred,
            const float4* __restrict__ gt,
            float* __restrict__ out,
            int out_elems) {
    const int wic  = threadIdx.x >> 5;   // warp in CTA: 0..3
    const int lane = threadIdx.x & 31;
    const int pair = wic >> 1;           // GT slot within CTA: 0..1
    const int half = wic & 1;            // which half of Q this warp scans
    const int gt_lin = blockIdx.x * 2 + pair;        // 0..4095
    const int b = gt_lin >> 7;
    const int g = gt_lin & (G_ - 1);

    const float4* __restrict__ pb = pred + (size_t)b * Q_;
    const float4 gv = gt[gt_lin];
    const float4* __restrict__ ph = pb + half * HALF_Q;
    const int ibase0 = half * HALF_Q;

    // ---- Warm-start: pool = exact sort of this warp's first 32 candidates. --
    uint64_t pool, curmax;
    float t2pad;
    {
        const int ci = ibase0 + lane;
        const float4 cp = __ldg(pb + ci);
        float d2e; EXACTD2(d2e, cp, gv)
        pool = sort32_asc(((uint64_t)__float_as_uint(d2e) << 32) | (unsigned)ci,
                          lane);
        curmax = __shfl_sync(FULLM, pool, 31);
        t2pad = __fadd_rn(__uint_as_float((unsigned)(curmax >> 32)), PADF);
    }

    // ---- Stage 1: screen with FFMA chain; on hit, reload chunk (L1-hot) ----
    // and verify+insert on exact rn-chain keys. Screening consumes the loads
    // so p0..p3 die early -> low register pressure.
    for (int t = 0; t < GROUPS; t++) {
        const float4* gp = ph + t * 128 + lane;
        float v0, v1, v2, v3;
        {
            const float4 p0 = __ldg(gp);
            const float4 p1 = __ldg(gp + 32);
            const float4 p2 = __ldg(gp + 64);
            const float4 p3 = __ldg(gp + 96);
            SCREEND2(v0, p0, gv) SCREEND2(v1, p1, gv)
            SCREEND2(v2, p2, gv) SCREEND2(v3, p3, gv)
        }

        const float vmin = fminf(fminf(v0, v1), fminf(v2, v3));
        if (__any_sync(FULLM, vmin <= t2pad)) {
            const int base = ibase0 + t * 128;
            #define CHUNK(J, VJ)                                               \
            {                                                                  \
                unsigned m = __ballot_sync(FULLM, VJ <= t2pad);                \
                if (t == 0 && J == 0) m = 0;  /* warm-start set: skip */       \
                if (m) {                                                       \
                    const float4 cp = __ldg(gp + J * 32);  /* L1-hot reload */ \
                    float d2e; EXACTD2(d2e, cp, gv)        /* exact verify */  \
                    while (m) {                                                \
                        const int src = __ffs(m) - 1;                          \
                        m &= m - 1;                                            \
                        const float ce = __shfl_sync(FULLM, d2e, src);         \
                        const unsigned ci = (unsigned)(base + J * 32 + src);   \
                        const uint64_t cand =                                  \
                            ((uint64_t)__float_as_uint(ce) << 32) | ci;        \
                        if (cand < curmax) {      /* warp-uniform exact */     \
                            const unsigned gtm =                               \
                                __ballot_sync(FULLM, pool > cand);             \
                            const uint64_t prev =                              \
                                __shfl_up_sync(FULLM, pool, 1);                \
                            const int ppos = __ffs(gtm) - 1;                   \
                            if (pool > cand)                                   \
                                pool = (lane == ppos) ? cand : prev;           \
                            curmax = __shfl_sync(FULLM, pool, 31);             \
                            t2pad = __fadd_rn(                                 \
                                __uint_as_float((unsigned)(curmax >> 32)),     \
                                PADF);                                         \
                        }                                                      \
                    }                                                          \
                }                                                              \
            }
            CHUNK(0, v0) CHUNK(1, v1) CHUNK(2, v2) CHUNK(3, v3)
            #undef CHUNK
        }
    }

    // ---- Merge the two half-pools (exact): lower half of bitonic merge. ----
    __shared__ uint64_t sp[2][32];
    if (half == 1) sp[pair][lane] = pool;
    __syncthreads();
    if (half == 1) return;

    {
        const uint64_t bk = sp[pair][31 - lane];  // other pool, reversed
        uint64_t v = (pool < bk) ? pool : bk;     // 32 smallest; bitonic seq
        #pragma unroll
        for (int j = 16; j; j >>= 1) {            // clean -> sorted ascending
            const uint64_t o = __shfl_xor_sync(FULLM, v, j);
            const uint64_t mnv = (v < o) ? v : o;
            const uint64_t mxv = (v < o) ? o : v;
            v = ((lane & j) == 0) ? mnv : mxv;
        }
        pool = v;
    }

    // ---- Re-rank by (sqrt(d2) bits, idx) == JAX's (d, idx); full sort. ------
    unsigned pidx = (unsigned)(pool & 0xFFFFFFFFull);
    {
        const float dval = __fsqrt_rn(__uint_as_float((unsigned)(pool >> 32)));
        const uint64_t skey = sort32_asc(
            ((uint64_t)__float_as_uint(dval) << 32) | pidx, lane);
        pidx = (unsigned)(skey & 0xFFFFFFFFull);
    }
    const int rank = lane;                        // 0 = nearest

    // ---- Stage 2: IoU(gt, candidate), explicit rn ops (no contraction). -----
    const float4 p = __ldg(pb + pidx);
    const float gx0 = __fsub_rn(gv.x, __fmul_rn(0.5f, gv.z));
    const float gx1 = __fadd_rn(gv.x, __fmul_rn(0.5f, gv.z));
    const float gy0 = __fsub_rn(gv.y, __fmul_rn(0.5f, gv.w));
    const float gy1 = __fadd_rn(gv.y, __fmul_rn(0.5f, gv.w));
    const float px0 = __fsub_rn(p.x,  __fmul_rn(0.5f, p.z));
    const float px1 = __fadd_rn(p.x,  __fmul_rn(0.5f, p.z));
    const float py0 = __fsub_rn(p.y,  __fmul_rn(0.5f, p.w));
    const float py1 = __fadd_rn(p.y,  __fmul_rn(0.5f, p.w));

    const float ltx = fmaxf(gx0, px0), lty = fmaxf(gy0, py0);
    const float rbx = fminf(gx1, px1), rby = fminf(gy1, py1);
    const float iw = fmaxf(__fsub_rn(rbx, ltx), 0.0f);
    const float ih = fmaxf(__fsub_rn(rby, lty), 0.0f);
    const float inter = __fmul_rn(iw, ih);
    const float areaA = __fmul_rn(__fsub_rn(gx1, gx0), __fsub_rn(gy1, gy0));
    const float areaB = __fmul_rn(__fsub_rn(px1, px0), __fsub_rn(py1, py0));
    const float uni   = __fsub_rn(__fadd_rn(areaA, areaB), inter);
    const float iou   = __fdiv_rn(inter, uni);

    // ---- top-9 by IoU, ties -> smaller rank: descending bitonic sort. -------
    uint64_t ikey = ((uint64_t)__float_as_uint(iou) << 32)
                  | (unsigned)(32 - rank);
    #pragma unroll
    for (int k = 2; k <= 32; k <<= 1) {
        #pragma unroll
        for (int j = k >> 1; j; j >>= 1) {
            const uint64_t o = __shfl_xor_sync(FULLM, ikey, j);
            const bool lower = (lane & j) == 0;
            const bool desc  = (lane & k) == 0;
            const uint64_t mnv = (ikey < o) ? ikey : o;
            const uint64_t mxv = (ikey < o) ? o : ikey;
            ikey = (lower == desc) ? mxv : mnv;   // descending
        }
    }
    const int rsel = 32 - (int)(ikey & 63);       // original rank of entry
    const unsigned psel = __shfl_sync(FULLM, pidx, rsel);

    const int obase = gt_lin * N_;
    if (lane < N_ && obase + lane < out_elems)
        out[obase + lane] = (float)psel;
    const int gbase = B_ * G_ * N_ + obase;
    if (lane < N_ && gbase + lane < out_elems)
        out[gbase + lane] = (float)g;
}

extern "C" void kernel_launch(void* const* d_in, const int* in_sizes, int n_in,
                              void* d_out, int out_size) {
    const float4* pred = (const float4*)d_in[0];
    const float4* gt   = (const float4*)d_in[1];
    if (n_in >= 2 && in_sizes[0] < in_sizes[1]) {   // robust input ordering
        pred = (const float4*)d_in[1];
        gt   = (const float4*)d_in[0];
    }
    // 2 GTs per CTA (4 warps: 2 warps per GT), 4096 GTs -> 2048 CTAs
    atss_kernel<<<(B_ * G_) / 2, 128>>>(pred, gt, (float*)d_out, out_size);
}

// round 17
// speedup vs baseline: 1.2981x; 1.2981x over previous
#include <cuda_runtime.h>
#include <cstdint>

constexpr int B_ = 32;
constexpr int Q_ = 16384;
constexpr int G_ = 128;
constexpr int N_ = 9;
constexpr int HALF_Q = Q_ / 2;         // 8192 per warp
constexpr int GROUPS = HALF_Q / 128;   // 64 groups of 4x32 candidates

#define FULLM 0xFFFFFFFFu
#define PADF  1e-5f   // >> worst-case |screen d2 - rn-chain d2| (~2e-6), d2<=4

// ---- f32x2 packed helpers (sm_103a) ----------------------------------------
__device__ __forceinline__ uint64_t pk2(float lo, float hi) {
    uint64_t r;
    asm("mov.b64 %0, {%1, %2};" : "=l"(r)
        : "r"(__float_as_uint(lo)), "r"(__float_as_uint(hi)));
    return r;
}
__device__ __forceinline__ void upk2(uint64_t v, float& lo, float& hi) {
    unsigned a, b;
    asm("mov.b64 {%0, %1}, %2;" : "=r"(a), "=r"(b) : "l"(v));
    lo = __uint_as_float(a); hi = __uint_as_float(b);
}
__device__ __forceinline__ uint64_t add2(uint64_t a, uint64_t b) {
    uint64_t r; asm("add.rn.f32x2 %0, %1, %2;" : "=l"(r) : "l"(a), "l"(b));
    return r;
}
__device__ __forceinline__ uint64_t mul2(uint64_t a, uint64_t b) {
    uint64_t r; asm("mul.rn.f32x2 %0, %1, %2;" : "=l"(r) : "l"(a), "l"(b));
    return r;
}
__device__ __forceinline__ uint64_t fma2(uint64_t a, uint64_t b, uint64_t c) {
    uint64_t r;
    asm("fma.rn.f32x2 %0, %1, %2, %3;" : "=l"(r) : "l"(a), "l"(b), "l"(c));
    return r;
}

// Full ascending bitonic sort of one 64-bit key per lane.
__device__ __forceinline__ uint64_t sort32_asc(uint64_t skey, int lane) {
#pragma unroll
    for (int k = 2; k <= 32; k <<= 1) {
#pragma unroll
        for (int j = k >> 1; j; j >>= 1) {
            const uint64_t o = __shfl_xor_sync(FULLM, skey, j);
            const bool lower = (lane & j) == 0;
            const bool asc   = (lane & k) == 0;
            const uint64_t mnv = (skey < o) ? skey : o;
            const uint64_t mxv = (skey < o) ? o : skey;
            skey = (lower == asc) ? mnv : mxv;
        }
    }
    return skey;
}

// Exact XLA-matching rn-chain d2 (no contraction).
#define EXACTD2(dst, P, GV) { \
    const float dx_ = __fsub_rn((GV).x, (P).x); \
    const float dy_ = __fsub_rn((GV).y, (P).y); \
    const float dw_ = __fsub_rn((GV).z, (P).z); \
    const float dh_ = __fsub_rn((GV).w, (P).w); \
    dst = __fadd_rn(__fadd_rn(__fadd_rn( \
              __fmul_rn(dx_, dx_), __fmul_rn(dy_, dy_)), \
              __fmul_rn(dw_, dw_)), __fmul_rn(dh_, dh_)); }

// Packed screening d2: (x,y)/(z,w) of a float4 are aligned register pairs,
// so no packing movs are needed in the loop. 5 ops per candidate.
#define SCREEND2X2(dst, P, NGXY, NGZW) { \
    const uint64_t dxy_ = add2(*(const uint64_t*)&(P).x, NGXY); \
    const uint64_t dzw_ = add2(*(const uint64_t*)&(P).z, NGZW); \
    const uint64_t s_   = fma2(dzw_, dzw_, mul2(dxy_, dxy_)); \
    float lo_, hi_; upk2(s_, lo_, hi_); \
    dst = __fadd_rn(lo_, hi_); }

__global__ void __launch_bounds__(128)
atss_kernel(const float4* __restrict__ pred,
            const float4* __restrict__ gt,
            float* __restrict__ out,
            int out_elems) {
    const int wic  = threadIdx.x >> 5;   // warp in CTA: 0..3
    const int lane = threadIdx.x & 31;
    const int pair = wic >> 1;           // GT slot within CTA: 0..1
    const int half = wic & 1;            // which half of Q this warp scans
    const int gt_lin = blockIdx.x * 2 + pair;        // 0..4095
    const int b = gt_lin >> 7;
    const int g = gt_lin & (G_ - 1);

    const float4* __restrict__ pb = pred + (size_t)b * Q_;
    const float4 gv = gt[gt_lin];
    const float4* __restrict__ ph = pb + half * HALF_Q;
    const int ibase0 = half * HALF_Q;

    // Packed negated gt coords (computed once).
    const uint64_t ngxy = pk2(-gv.x, -gv.y);
    const uint64_t ngzw = pk2(-gv.z, -gv.w);

    // ---- Warm-start: pool = exact sort of this warp's first 32 candidates. --
    uint64_t pool;
    float t2pad;
    {
        const int ci = ibase0 + lane;
        const float4 cp = __ldg(pb + ci);
        float d2e; EXACTD2(d2e, cp, gv)
        pool = sort32_asc(((uint64_t)__float_as_uint(d2e) << 32) | (unsigned)ci,
                          lane);
        const uint64_t cm = __shfl_sync(FULLM, pool, 31);
        t2pad = __fadd_rn(__uint_as_float((unsigned)(cm >> 32)), PADF);
    }

    // ---- Stage 1: f32x2 screen; exact rn-chain verify + self-guarded -------
    // sorted-shift insert; threshold refreshed once per hit-chunk.
    for (int t = 0; t < GROUPS; t++) {
        const float4* gp = ph + t * 128 + lane;
        const float4 p0 = __ldg(gp);
        const float4 p1 = __ldg(gp + 32);
        const float4 p2 = __ldg(gp + 64);
        const float4 p3 = __ldg(gp + 96);

        float v0, v1, v2, v3;
        SCREEND2X2(v0, p0, ngxy, ngzw) SCREEND2X2(v1, p1, ngxy, ngzw)
        SCREEND2X2(v2, p2, ngxy, ngzw) SCREEND2X2(v3, p3, ngxy, ngzw)

        const float vmin = fminf(fminf(v0, v1), fminf(v2, v3));
        if (__any_sync(FULLM, vmin <= t2pad)) {
            const int base = ibase0 + t * 128;
            #define CHUNK(J, VJ, PJ)                                           \
            {                                                                  \
                unsigned m = __ballot_sync(FULLM, VJ <= t2pad);                \
                if (t == 0 && J == 0) m = 0;  /* warm-start set: skip */       \
                if (m) {                                                       \
                    float d2e; EXACTD2(d2e, PJ, gv)   /* exact, in-register */ \
                    while (m) {                                                \
                        const int src = __ffs(m) - 1;                          \
                        m &= m - 1;                                            \
                        const float ce = __shfl_sync(FULLM, d2e, src);         \
                        const unsigned ci = (unsigned)(base + J * 32 + src);   \
                        const uint64_t cand =                                  \
                            ((uint64_t)__float_as_uint(ce) << 32) | ci;        \
                        /* self-guarded sorted-shift insert */                 \
                        const unsigned gtm =                                   \
                            __ballot_sync(FULLM, pool > cand);                 \
                        const uint64_t prev =                                  \
                            __shfl_up_sync(FULLM, pool, 1);                    \
                        const int ppos = __ffs(gtm) - 1;                       \
                        if (pool > cand)                                       \
                            pool = (lane == ppos) ? cand : prev;               \
                    }                                                          \
                    const uint64_t cm = __shfl_sync(FULLM, pool, 31);          \
                    t2pad = __fadd_rn(                                         \
                        __uint_as_float((unsigned)(cm >> 32)), PADF);          \
                }                                                              \
            }
            CHUNK(0, v0, p0) CHUNK(1, v1, p1) CHUNK(2, v2, p2) CHUNK(3, v3, p3)
            #undef CHUNK
        }
    }

    // ---- Merge the two half-pools (exact): lower half of bitonic merge. ----
    __shared__ uint64_t sp[2][32];
    if (half == 1) sp[pair][lane] = pool;
    __syncthreads();
    if (half == 1) return;

    {
        const uint64_t bk = sp[pair][31 - lane];  // other pool, reversed
        uint64_t v = (pool < bk) ? pool : bk;     // 32 smallest; bitonic seq
        #pragma unroll
        for (int j = 16; j; j >>= 1) {            // clean -> sorted ascending
            const uint64_t o = __shfl_xor_sync(FULLM, v, j);
            const uint64_t mnv = (v < o) ? v : o;
            const uint64_t mxv = (v < o) ? o : v;
            v = ((lane & j) == 0) ? mnv : mxv;
        }
        pool = v;
    }

    // ---- Re-rank by (sqrt(d2) bits, idx) == JAX's (d, idx); full sort. ------
    unsigned pidx = (unsigned)(pool & 0xFFFFFFFFull);
    {
        const float dval = __fsqrt_rn(__uint_as_float((unsigned)(pool >> 32)));
        const uint64_t skey = sort32_asc(
            ((uint64_t)__float_as_uint(dval) << 32) | pidx, lane);
        pidx = (unsigned)(skey & 0xFFFFFFFFull);
    }
    const int rank = lane;                        // 0 = nearest

    // ---- Stage 2: IoU(gt, candidate), explicit rn ops (no contraction). -----
    const float4 p = __ldg(pb + pidx);
    const float gx0 = __fsub_rn(gv.x, __fmul_rn(0.5f, gv.z));
    const float gx1 = __fadd_rn(gv.x, __fmul_rn(0.5f, gv.z));
    const float gy0 = __fsub_rn(gv.y, __fmul_rn(0.5f, gv.w));
    const float gy1 = __fadd_rn(gv.y, __fmul_rn(0.5f, gv.w));
    const float px0 = __fsub_rn(p.x,  __fmul_rn(0.5f, p.z));
    const float px1 = __fadd_rn(p.x,  __fmul_rn(0.5f, p.z));
    const float py0 = __fsub_rn(p.y,  __fmul_rn(0.5f, p.w));
    const float py1 = __fadd_rn(p.y,  __fmul_rn(0.5f, p.w));

    const float ltx = fmaxf(gx0, px0), lty = fmaxf(gy0, py0);
    const float rbx = fminf(gx1, px1), rby = fminf(gy1, py1);
    const float iw = fmaxf(__fsub_rn(rbx, ltx), 0.0f);
    const float ih = fmaxf(__fsub_rn(rby, lty), 0.0f);
    const float inter = __fmul_rn(iw, ih);
    const float areaA = __fmul_rn(__fsub_rn(gx1, gx0), __fsub_rn(gy1, gy0));
    const float areaB = __fmul_rn(__fsub_rn(px1, px0), __fsub_rn(py1, py0));
    const float uni   = __fsub_rn(__fadd_rn(areaA, areaB), inter);
    const float iou   = __fdiv_rn(inter, uni);

    // ---- top-9 by IoU, ties -> smaller rank: descending bitonic sort. -------
    uint64_t ikey = ((uint64_t)__float_as_uint(iou) << 32)
                  | (unsigned)(32 - rank);
    #pragma unroll
    for (int k = 2; k <= 32; k <<= 1) {
        #pragma unroll
        for (int j = k >> 1; j; j >>= 1) {
            const uint64_t o = __shfl_xor_sync(FULLM, ikey, j);
            const bool lower = (lane & j) == 0;
            const bool desc  = (lane & k) == 0;
            const uint64_t mnv = (ikey < o) ? ikey : o;
            const uint64_t mxv = (ikey < o) ? o : ikey;
            ikey = (lower == desc) ? mxv : mnv;   // descending
        }
    }
    const int rsel = 32 - (int)(ikey & 63);       // original rank of entry
    const unsigned psel = __shfl_sync(FULLM, pidx, rsel);

    const int obase = gt_lin * N_;
    if (lane < N_ && obase + lane < out_elems)
        out[obase + lane] = (float)psel;
    const int gbase = B_ * G_ * N_ + obase;
    if (lane < N_ && gbase + lane < out_elems)
        out[gbase + lane] = (float)g;
}

extern "C" void kernel_launch(void* const* d_in, const int* in_sizes, int n_in,
                              void* d_out, int out_size) {
    const float4* pred = (const float4*)d_in[0];
    const float4* gt   = (const float4*)d_in[1];
    if (n_in >= 2 && in_sizes[0] < in_sizes[1]) {   // robust input ordering
        pred = (const float4*)d_in[1];
        gt   = (const float4*)d_in[0];
    }
    // 2 GTs per CTA (4 warps: 2 warps per GT), 4096 GTs -> 2048 CTAs
    atss_kernel<<<(B_ * G_) / 2, 128>>>(pred, gt, (float*)d_out, out_size);
}